// round 14
// baseline (speedup 1.0000x reference)
#include <cuda_runtime.h>
#include <cuda_fp16.h>
#include <cstdint>

// SecureSwishFeedForward via fp16 mma.sync (m16n8k16), fp32 accumulate.
// (Harness PTX stage targets compute_103 base — no tcgen05; mbarrier +
// cp.async.mbarrier.arrive are base sm_80/90 PTX and do compile.)
//
// out = swish_poly(X @ W1^T + b1) @ W2^T + b2
// X:[8192,1024] W1:[4096,1024] W2:[1024,4096], fp32 row-major, K contiguous.
//
// R14: mbarrier-decoupled pipeline — zero __syncthreads in the mainloop.
//  full[s]  (cnt 256): cp.async.mbarrier.arrive.noinc per thread; consumers
//                      try_wait parity per warp (HW completion, no warp sync).
//  empty[s] (cnt 256): per-thread arrive after last read; producer waits with
//                      ~half-iteration slack. Warps free-run across the ring.

#define BM 128
#define BN 128
#define BKH 64                               // K halves per stage (128 B/row)
#define PADH 8
#define LDSS (BKH + PADH)                    // 72 halves = 144 B row stride
#define A_STAGE_H (BM * LDSS)                // 9216 halves
#define A_STAGE_BYTES (A_STAGE_H * 2)        // 18432
#define STAGE_BYTES (2 * A_STAGE_BYTES)      // 36864
#define STAGES 3
#define NTHREADS 256
#define SMEM_DYN (STAGES * STAGE_BYTES)      // 110592

__device__ __align__(16) __half g_midh[8192UL * 4096UL];
__device__ __align__(16) __half g_Xh  [8192UL * 1024UL];
__device__ __align__(16) __half g_W1h [4096UL * 1024UL];
__device__ __align__(16) __half g_W2h [1024UL * 4096UL];

__device__ __forceinline__ uint32_t stou(const void* p) {
    uint32_t a;
    asm("{ .reg .u64 t; cvta.to.shared.u64 t, %1; cvt.u32.u64 %0, t; }"
        : "=r"(a) : "l"(p));
    return a;
}

__device__ __forceinline__ void cpa16(const __half* smem_dst, const __half* gsrc) {
    uint32_t a = stou(smem_dst);
    asm volatile("cp.async.cg.shared.global [%0], [%1], 16;" :: "r"(a), "l"(gsrc));
}

#define LDSM4(r, addr) \
    asm volatile("ldmatrix.sync.aligned.m8n8.x4.shared.b16 {%0,%1,%2,%3}, [%4];" \
                 : "=r"((r)[0]), "=r"((r)[1]), "=r"((r)[2]), "=r"((r)[3])       \
                 : "r"(addr))

#define MBAR_INIT(a, n) \
    asm volatile("mbarrier.init.shared.b64 [%0], %1;" :: "r"(a), "r"((uint32_t)(n)) : "memory")
#define MBAR_ARRIVE(a) \
    asm volatile("{ .reg .b64 t; mbarrier.arrive.shared.b64 t, [%0]; }" :: "r"(a) : "memory")
#define CPA_MBAR_ARRIVE(a) \
    asm volatile("cp.async.mbarrier.arrive.noinc.shared.b64 [%0];" :: "r"(a) : "memory")

__device__ __forceinline__ void mbar_wait(uint32_t addr, uint32_t parity) {
    asm volatile(
        "{\n\t.reg .pred P;\n\t"
        "LW%=:\n\t"
        "mbarrier.try_wait.parity.shared.b64 P, [%0], %1;\n\t"
        "@P bra LD%=;\n\t"
        "bra LW%=;\n\t"
        "LD%=:\n\t}"
        :: "r"(addr), "r"(parity) : "memory");
}

template<bool SWISH, bool HALF_OUT>
__global__ __launch_bounds__(NTHREADS, 2)
void ffn_gemm(const __half* __restrict__ A,   // [M, K] fp16
              const __half* __restrict__ B,   // [N, K] fp16
              const float* __restrict__ bias, // [N] fp32
              void* __restrict__ Cv,          // [M, N] half or float
              int M, int N, int K)
{
    extern __shared__ __align__(16) __half smem[];
    __shared__ __align__(8) uint64_t s_mbar[2 * STAGES];  // full[0..2], empty[0..2]
    const uint32_t smem_u32 = stou(smem);

    const int tid  = threadIdx.x;
    const int wid  = tid >> 5, lane = tid & 31;
    const int wr   = wid >> 2, wc   = wid & 3;   // 2x4 warp grid -> 64x32 warp tile
    const int lr   = lane >> 2, lc  = lane & 3;
    const int rowBase = blockIdx.y * BM;
    const int colBase = blockIdx.x * BN;
    const int NC = K / BKH;

    uint32_t mb_full[STAGES], mb_empty[STAGES];
#pragma unroll
    for (int s = 0; s < STAGES; s++) {
        mb_full[s]  = stou(&s_mbar[s]);
        mb_empty[s] = stou(&s_mbar[STAGES + s]);
    }
    if (tid == 0) {
#pragma unroll
        for (int s = 0; s < STAGES; s++) {
            MBAR_INIT(mb_full[s],  NTHREADS);
            MBAR_INIT(mb_empty[s], NTHREADS);
        }
    }
    __syncthreads();   // only CTA-wide barrier in the kernel

    // ldmatrix lane addressing (byte offsets within a stage).
    const int t8  = lane & 7;
    const int tb3 = (lane >> 3) & 1;
    const int tb4 = (lane >> 4) & 1;
    uint32_t a_off[4], b_off[2];
#pragma unroll
    for (int mi = 0; mi < 4; mi++)
        a_off[mi] = (uint32_t)((wr * 64 + mi * 16 + t8 + tb3 * 8) * (LDSS * 2) + tb4 * 16);
#pragma unroll
    for (int p = 0; p < 2; p++)
        b_off[p] = (uint32_t)(A_STAGE_BYTES +
                              (wc * 32 + p * 16 + t8 + tb4 * 8) * (LDSS * 2) + tb3 * 16);

    float acc[4][4][4];
#pragma unroll
    for (int mi = 0; mi < 4; mi++)
#pragma unroll
        for (int ni = 0; ni < 4; ni++)
#pragma unroll
            for (int e = 0; e < 4; e++) acc[mi][ni][e] = 0.0f;

    const int ldrow = tid >> 3;
    const int ldq   = (tid & 7) * 8;             // half offset within row
    const __half* aLd = A + (size_t)(rowBase + ldrow) * K + ldq;
    const __half* bLd = B + (size_t)(colBase + ldrow) * K + ldq;

    #define LOAD_STAGE(s, aP, bP) do {                                         \
        __half* sa_ = smem + (s) * (STAGE_BYTES / 2);                          \
        __half* sb_ = sa_ + A_STAGE_H;                                         \
        _Pragma("unroll")                                                      \
        for (int it_ = 0; it_ < 4; it_++)                                      \
            cpa16(sa_ + (ldrow + it_ * 32) * LDSS + ldq,                       \
                  (aP) + (size_t)(it_ * 32) * K);                              \
        _Pragma("unroll")                                                      \
        for (int it_ = 0; it_ < 4; it_++)                                      \
            cpa16(sb_ + (ldrow + it_ * 32) * LDSS + ldq,                       \
                  (bP) + (size_t)(it_ * 32) * K);                              \
    } while (0)

    #define LOADA_ONE(sb_addr, s, mi_, afb) \
        LDSM4((afb)[mi_], (sb_addr) + a_off[mi_] + (s) * 32)

    #define LOADB(sb_addr, s, bfb) do {                                        \
        _Pragma("unroll")                                                      \
        for (int p_ = 0; p_ < 2; p_++)                                         \
            LDSM4((bfb)[p_], (sb_addr) + b_off[p_] + (s) * 32);                \
    } while (0)

    #define MMA_ROW(mi_, afrag, bfb) do {                                      \
        _Pragma("unroll")                                                      \
        for (int ni_ = 0; ni_ < 4; ni_++)                                      \
            asm volatile(                                                      \
                "mma.sync.aligned.m16n8k16.row.col.f32.f16.f16.f32 "           \
                "{%0,%1,%2,%3}, {%4,%5,%6,%7}, {%8,%9}, {%0,%1,%2,%3};"        \
                : "+f"(acc[mi_][ni_][0]), "+f"(acc[mi_][ni_][1]),              \
                  "+f"(acc[mi_][ni_][2]), "+f"(acc[mi_][ni_][3])               \
                : "r"((afrag)[0]), "r"((afrag)[1]),                            \
                  "r"((afrag)[2]), "r"((afrag)[3]),                            \
                  "r"((bfb)[ni_ >> 1][(ni_ & 1) * 2]),                         \
                  "r"((bfb)[ni_ >> 1][(ni_ & 1) * 2 + 1]));                    \
    } while (0)

    // Prologue: produce stages 0 and 1 (buffers virgin, no empty wait).
    LOAD_STAGE(0, aLd, bLd); aLd += BKH; bLd += BKH;
    CPA_MBAR_ARRIVE(mb_full[0]);
    LOAD_STAGE(1, aLd, bLd); aLd += BKH; bLd += BKH;
    CPA_MBAR_ARRIVE(mb_full[1]);

    // Wait stage 0 ready (HW arrivals), prefetch its k0 fragments.
    mbar_wait(mb_full[0], 0);
    uint32_t af[4][4];            // A: single-buffered, JIT reloaded
    uint32_t bf[2][2][4];         // B: double-buffered
#pragma unroll
    for (int mi = 0; mi < 4; mi++) LOADA_ONE(smem_u32, 0, mi, af);
    LOADB(smem_u32, 0, bf[0]);

    // Consumer cursor: stage c -> slot, parity ph = (c/3)&1.
    // Producer cursor: stage c+2 -> pslot, pph = parity of its empty-wait.
    int slot = 0, ph = 0;
    int pslot = 2, pph = 1;       // so first wrap (c=1 -> stage 3) gives parity 0

    for (int c = 0; c < NC; c++) {
        const uint32_t sbase = smem_u32 + slot * STAGE_BYTES;

#pragma unroll
        for (int s = 0; s < 4; s++) {             // 4 k16 steps (BKH=64)
            const int cur = s & 1;
            if (s < 3) LOADB(sbase, s + 1, bf[cur ^ 1]);
#pragma unroll
            for (int mi = 0; mi < 4; mi++) {
                MMA_ROW(mi, af[mi], bf[cur]);
                if (s < 3) LOADA_ONE(sbase, s + 1, mi, af);
            }
            // Produce stage c+2 mid-iteration: empty-wait has ~half an
            // iteration of slack vs all warps' end-of-prev-iter arrivals.
            if (s == 0 && c + 2 < NC) {
                if (c >= 1) mbar_wait(mb_empty[pslot], (uint32_t)pph);
                LOAD_STAGE(pslot, aLd, bLd);
                aLd += BKH; bLd += BKH;
                CPA_MBAR_ARRIVE(mb_full[pslot]);
            }
        }

        // All fragment reads of stage c are consumed by the MMAs above.
        MBAR_ARRIVE(mb_empty[slot]);

        // Prefetch next stage's k0 fragments (per-warp wait on HW arrivals).
        if (c + 1 < NC) {
            const int ns = (slot == 2) ? 0 : slot + 1;
            const int np = (slot == 2) ? (ph ^ 1) : ph;
            mbar_wait(mb_full[ns], (uint32_t)np);
            const uint32_t snext = smem_u32 + ns * STAGE_BYTES;
#pragma unroll
            for (int mi = 0; mi < 4; mi++) LOADA_ONE(snext, 0, mi, af);
            LOADB(snext, 0, bf[0]);
        }

        if (++slot == STAGES)  { slot = 0;  ph ^= 1; }
        if (++pslot == STAGES) { pslot = 0; pph ^= 1; }
    }

    // Epilogue: bias + optional poly-swish; store half (mid) or float (out).
#pragma unroll
    for (int ni = 0; ni < 4; ni++) {
        const int col = colBase + wc * 32 + ni * 8 + 2 * lc;
        const float bv0 = __ldg(bias + col);
        const float bv1 = __ldg(bias + col + 1);
#pragma unroll
        for (int mi = 0; mi < 4; mi++) {
#pragma unroll
            for (int h = 0; h < 2; h++) {
                const int row = rowBase + wr * 64 + mi * 16 + lr + h * 8;
                float v0 = acc[mi][ni][2 * h]     + bv0;
                float v1 = acc[mi][ni][2 * h + 1] + bv1;
                if (SWISH) {
                    float s0 = fmaf(-0.0208f * v0 * v0, v0, fmaf(0.25f, v0, 0.5f));
                    float s1 = fmaf(-0.0208f * v1 * v1, v1, fmaf(0.25f, v1, 0.5f));
                    v0 *= s0; v1 *= s1;
                }
                if (HALF_OUT) {
                    __half* C = (__half*)Cv;
                    *reinterpret_cast<__half2*>(C + (size_t)row * N + col) =
                        __floats2half2_rn(v0, v1);
                } else {
                    float* C = (float*)Cv;
                    *reinterpret_cast<float2*>(C + (size_t)row * N + col) =
                        make_float2(v0, v1);
                }
            }
        }
    }
}

// -------------------- fused fp32 -> fp16 pre-pass ---------------------------

struct __align__(16) Half8 { __half2 a, b, c, d; };

__global__ void to_half_fused(const float4* __restrict__ x,  __half* __restrict__ xh,  int n1,
                              const float4* __restrict__ w1, __half* __restrict__ w1h, int n2,
                              const float4* __restrict__ w2, __half* __restrict__ w2h, int n3)
{
    int i = blockIdx.x * blockDim.x + threadIdx.x;   // group of 8 floats
    const float4* src; __half* dst; int j;
    if (i < n1)                { src = x;  dst = xh;  j = i; }
    else if (i < n1 + n2)      { src = w1; dst = w1h; j = i - n1; }
    else if (i < n1 + n2 + n3) { src = w2; dst = w2h; j = i - n1 - n2; }
    else return;
    float4 v0 = src[j * 2];
    float4 v1 = src[j * 2 + 1];
    Half8 pack;
    pack.a = __floats2half2_rn(v0.x, v0.y);
    pack.b = __floats2half2_rn(v0.z, v0.w);
    pack.c = __floats2half2_rn(v1.x, v1.y);
    pack.d = __floats2half2_rn(v1.z, v1.w);
    *reinterpret_cast<Half8*>(dst + (size_t)j * 8) = pack;
}

// ------------------------------- launch -------------------------------------

extern "C" void kernel_launch(void* const* d_in, const int* in_sizes, int n_in,
                              void* d_out, int out_size)
{
    const float* X  = (const float*)d_in[0]; // [M, D]
    const float* W1 = (const float*)d_in[1]; // [F, D]
    const float* b1 = (const float*)d_in[2]; // [F]
    const float* W2 = (const float*)d_in[3]; // [D, F]
    const float* b2 = (const float*)d_in[4]; // [D]
    float* out = (float*)d_out;              // [M, D]

    const int F = in_sizes[2];               // 4096
    const int D = in_sizes[4];               // 1024
    const int M = in_sizes[0] / D;           // 8192

    __half *midh, *Xh, *W1h, *W2h;
    cudaGetSymbolAddress((void**)&midh, g_midh);
    cudaGetSymbolAddress((void**)&Xh,   g_Xh);
    cudaGetSymbolAddress((void**)&W1h,  g_W1h);
    cudaGetSymbolAddress((void**)&W2h,  g_W2h);

    cudaFuncSetAttribute(ffn_gemm<true,  true >,
                         cudaFuncAttributeMaxDynamicSharedMemorySize, SMEM_DYN);
    cudaFuncSetAttribute(ffn_gemm<false, false>,
                         cudaFuncAttributeMaxDynamicSharedMemorySize, SMEM_DYN);

    // Convert inputs to fp16 (RN). One launch; index = groups of 8 floats.
    const int n1 = (M * D) / 8, n2 = (F * D) / 8, n3 = (D * F) / 8;
    const int ntot = n1 + n2 + n3;
    to_half_fused<<<(ntot + 255) / 256, 256>>>(
        (const float4*)X,  Xh,  n1,
        (const float4*)W1, W1h, n2,
        (const float4*)W2, W2h, n3);

    // GEMM1: midh = half(swish(X @ W1^T + b1))   [M, F], K = D
    {
        dim3 grid(F / BN, M / BM);
        ffn_gemm<true, true><<<grid, NTHREADS, SMEM_DYN>>>(Xh, W1h, b1, midh, M, F, D);
    }
    // GEMM2: out = midh @ W2^T + b2               [M, D], K = F
    {
        dim3 grid(D / BN, M / BM);
        ffn_gemm<false, false><<<grid, NTHREADS, SMEM_DYN>>>(midh, W2h, b2, out, M, D, F);
    }
}

// round 15
// speedup vs baseline: 1.0644x; 1.0644x over previous
#include <cuda_runtime.h>
#include <cuda_fp16.h>
#include <cstdint>

// SecureSwishFeedForward via fp16 mma.sync (m16n8k16), fp32 accumulate.
// (Harness PTX stage targets compute_103 — no tcgen05.)
//
// out = swish_poly(X @ W1^T + b1) @ W2^T + b2
// X:[8192,1024] W1:[4096,1024] W2:[1024,4096], fp32 row-major, K contiguous.
//
// R15: R13 sync skeleton (cp.async 3-stage, wait_group 1, single
// __syncthreads/iter, cross-barrier fragment prefetch, A JIT single-buffer,
// B double-buffer) with the warp tile widened to 64x64:
//   4 warps/CTA (128 threads), warp grid 2x2, 32 HMMA per 8 LDSM per step
//   (ratio 4 vs 2.67), barrier spans 4 warps, occ 2 -> 8 warps/SM.

#define BM 128
#define BN 128
#define BKH 64                               // K halves per stage (128 B/row)
#define PADH 8
#define LDSS (BKH + PADH)                    // 72 halves = 144 B row stride
#define A_STAGE_H (BM * LDSS)                // 9216 halves
#define A_STAGE_BYTES (A_STAGE_H * 2)        // 18432
#define STAGE_BYTES (2 * A_STAGE_BYTES)      // 36864
#define STAGES 3
#define NTHREADS 128
#define SMEM_DYN (STAGES * STAGE_BYTES)      // 110592

__device__ __align__(16) __half g_midh[8192UL * 4096UL];
__device__ __align__(16) __half g_Xh  [8192UL * 1024UL];
__device__ __align__(16) __half g_W1h [4096UL * 1024UL];
__device__ __align__(16) __half g_W2h [1024UL * 4096UL];

__device__ __forceinline__ uint32_t stou(const void* p) {
    uint32_t a;
    asm("{ .reg .u64 t; cvta.to.shared.u64 t, %1; cvt.u32.u64 %0, t; }"
        : "=r"(a) : "l"(p));
    return a;
}

__device__ __forceinline__ void cpa16(const __half* smem_dst, const __half* gsrc) {
    uint32_t a = stou(smem_dst);
    asm volatile("cp.async.cg.shared.global [%0], [%1], 16;" :: "r"(a), "l"(gsrc));
}

#define LDSM4(r, addr) \
    asm volatile("ldmatrix.sync.aligned.m8n8.x4.shared.b16 {%0,%1,%2,%3}, [%4];" \
                 : "=r"((r)[0]), "=r"((r)[1]), "=r"((r)[2]), "=r"((r)[3])       \
                 : "r"(addr))

template<bool SWISH, bool HALF_OUT>
__global__ __launch_bounds__(NTHREADS, 2)
void ffn_gemm(const __half* __restrict__ A,   // [M, K] fp16
              const __half* __restrict__ B,   // [N, K] fp16
              const float* __restrict__ bias, // [N] fp32
              void* __restrict__ Cv,          // [M, N] half or float
              int M, int N, int K)
{
    extern __shared__ __align__(16) __half smem[];
    const uint32_t smem_u32 = stou(smem);

    const int tid  = threadIdx.x;
    const int wid  = tid >> 5, lane = tid & 31;
    const int wr   = wid >> 1, wc   = wid & 1;   // 2x2 warp grid -> 64x64 warp tile
    const int lr   = lane >> 2, lc  = lane & 3;
    const int rowBase = blockIdx.y * BM;
    const int colBase = blockIdx.x * BN;
    const int NC = K / BKH;

    // ldmatrix lane addressing (byte offsets within a stage).
    // A frag mi (m16k16): lane t: row += ((t>>3)&1)*8, kbyte += ((t>>4)&1)*16
    // B pair p (n16k16):  lane t: n   += ((t>>4)&1)*8, kbyte += ((t>>3)&1)*16
    const int t8  = lane & 7;
    const int tb3 = (lane >> 3) & 1;
    const int tb4 = (lane >> 4) & 1;
    uint32_t a_off[4], b_off[4];
#pragma unroll
    for (int mi = 0; mi < 4; mi++)
        a_off[mi] = (uint32_t)((wr * 64 + mi * 16 + t8 + tb3 * 8) * (LDSS * 2) + tb4 * 16);
#pragma unroll
    for (int p = 0; p < 4; p++)
        b_off[p] = (uint32_t)(A_STAGE_BYTES +
                              (wc * 64 + p * 16 + t8 + tb4 * 8) * (LDSS * 2) + tb3 * 16);

    float acc[4][8][4];
#pragma unroll
    for (int mi = 0; mi < 4; mi++)
#pragma unroll
        for (int ni = 0; ni < 8; ni++)
#pragma unroll
            for (int e = 0; e < 4; e++) acc[mi][ni][e] = 0.0f;

    // Per-thread incremental gmem pointers (advance BKH halves per stage).
    const int ldrow = tid >> 3;                  // 0..15
    const int ldq   = (tid & 7) * 8;             // half offset within row
    const __half* aLd = A + (size_t)(rowBase + ldrow) * K + ldq;
    const __half* bLd = B + (size_t)(colBase + ldrow) * K + ldq;

    #define LOAD_STAGE(s, aP, bP) do {                                         \
        __half* sa_ = smem + (s) * (STAGE_BYTES / 2);                          \
        __half* sb_ = sa_ + A_STAGE_H;                                         \
        _Pragma("unroll")                                                      \
        for (int it_ = 0; it_ < 8; it_++)                                      \
            cpa16(sa_ + (ldrow + it_ * 16) * LDSS + ldq,                       \
                  (aP) + (size_t)(it_ * 16) * K);                              \
        _Pragma("unroll")                                                      \
        for (int it_ = 0; it_ < 8; it_++)                                      \
            cpa16(sb_ + (ldrow + it_ * 16) * LDSS + ldq,                       \
                  (bP) + (size_t)(it_ * 16) * K);                              \
    } while (0)

    #define LOADA_ONE(sb_addr, s, mi_, afb) \
        LDSM4((afb)[mi_], (sb_addr) + a_off[mi_] + (s) * 32)

    #define LOADB(sb_addr, s, bfb) do {                                        \
        _Pragma("unroll")                                                      \
        for (int p_ = 0; p_ < 4; p_++)                                         \
            LDSM4((bfb)[p_], (sb_addr) + b_off[p_] + (s) * 32);                \
    } while (0)

    #define MMA_ROW(mi_, afrag, bfb) do {                                      \
        _Pragma("unroll")                                                      \
        for (int ni_ = 0; ni_ < 8; ni_++)                                      \
            asm volatile(                                                      \
                "mma.sync.aligned.m16n8k16.row.col.f32.f16.f16.f32 "           \
                "{%0,%1,%2,%3}, {%4,%5,%6,%7}, {%8,%9}, {%0,%1,%2,%3};"        \
                : "+f"(acc[mi_][ni_][0]), "+f"(acc[mi_][ni_][1]),              \
                  "+f"(acc[mi_][ni_][2]), "+f"(acc[mi_][ni_][3])               \
                : "r"((afrag)[0]), "r"((afrag)[1]),                            \
                  "r"((afrag)[2]), "r"((afrag)[3]),                            \
                  "r"((bfb)[ni_ >> 1][(ni_ & 1) * 2]),                         \
                  "r"((bfb)[ni_ >> 1][(ni_ & 1) * 2 + 1]));                    \
    } while (0)

    // Prologue: load stages 0 and 1; wait stage 0, barrier, prefetch s0 frags.
    LOAD_STAGE(0, aLd, bLd); aLd += BKH; bLd += BKH;
    asm volatile("cp.async.commit_group;" ::: "memory");
    LOAD_STAGE(1, aLd, bLd); aLd += BKH; bLd += BKH;
    asm volatile("cp.async.commit_group;" ::: "memory");
    asm volatile("cp.async.wait_group 1;" ::: "memory");
    __syncthreads();

    uint32_t af[4][4];            // A: single-buffered, JIT reloaded
    uint32_t bf[2][4][4];         // B: double-buffered (4 pairs)
#pragma unroll
    for (int mi = 0; mi < 4; mi++) LOADA_ONE(smem_u32, 0, mi, af);
    LOADB(smem_u32, 0, bf[0]);

    for (int c = 0; c < NC; c++) {
        const uint32_t sbase = smem_u32 + (c % STAGES) * STAGE_BYTES;
        const bool haveNextStage = (c + 2 < NC);

#pragma unroll
        for (int s = 0; s < 4; s++) {             // 4 k16 steps (BKH=64)
            const int cur = s & 1;
            if (s < 3) LOADB(sbase, s + 1, bf[cur ^ 1]);
#pragma unroll
            for (int mi = 0; mi < 4; mi++) {
                MMA_ROW(mi, af[mi], bf[cur]);
                if (s < 3) LOADA_ONE(sbase, s + 1, mi, af);
            }
            if (s == 0) {
                if (haveNextStage) {
                    LOAD_STAGE((c + 2) % STAGES, aLd, bLd);
                    aLd += BKH; bLd += BKH;
                }
                asm volatile("cp.async.commit_group;" ::: "memory");
            }
        }

        asm volatile("cp.async.wait_group 1;" ::: "memory");
        __syncthreads();
        if (c + 1 < NC) {
            const uint32_t snext = smem_u32 + ((c + 1) % STAGES) * STAGE_BYTES;
#pragma unroll
            for (int mi = 0; mi < 4; mi++) LOADA_ONE(snext, 0, mi, af);
            LOADB(snext, 0, bf[0]);
        }
    }

    // Epilogue: bias + optional poly-swish; store half (mid) or float (out).
#pragma unroll
    for (int ni = 0; ni < 8; ni++) {
        const int col = colBase + wc * 64 + ni * 8 + 2 * lc;
        const float bv0 = __ldg(bias + col);
        const float bv1 = __ldg(bias + col + 1);
#pragma unroll
        for (int mi = 0; mi < 4; mi++) {
#pragma unroll
            for (int h = 0; h < 2; h++) {
                const int row = rowBase + wr * 64 + mi * 16 + lr + h * 8;
                float v0 = acc[mi][ni][2 * h]     + bv0;
                float v1 = acc[mi][ni][2 * h + 1] + bv1;
                if (SWISH) {
                    float s0 = fmaf(-0.0208f * v0 * v0, v0, fmaf(0.25f, v0, 0.5f));
                    float s1 = fmaf(-0.0208f * v1 * v1, v1, fmaf(0.25f, v1, 0.5f));
                    v0 *= s0; v1 *= s1;
                }
                if (HALF_OUT) {
                    __half* C = (__half*)Cv;
                    *reinterpret_cast<__half2*>(C + (size_t)row * N + col) =
                        __floats2half2_rn(v0, v1);
                } else {
                    float* C = (float*)Cv;
                    *reinterpret_cast<float2*>(C + (size_t)row * N + col) =
                        make_float2(v0, v1);
                }
            }
        }
    }
}

// -------------------- fused fp32 -> fp16 pre-pass ---------------------------

struct __align__(16) Half8 { __half2 a, b, c, d; };

__global__ void to_half_fused(const float4* __restrict__ x,  __half* __restrict__ xh,  int n1,
                              const float4* __restrict__ w1, __half* __restrict__ w1h, int n2,
                              const float4* __restrict__ w2, __half* __restrict__ w2h, int n3)
{
    int i = blockIdx.x * blockDim.x + threadIdx.x;   // group of 8 floats
    const float4* src; __half* dst; int j;
    if (i < n1)                { src = x;  dst = xh;  j = i; }
    else if (i < n1 + n2)      { src = w1; dst = w1h; j = i - n1; }
    else if (i < n1 + n2 + n3) { src = w2; dst = w2h; j = i - n1 - n2; }
    else return;
    float4 v0 = src[j * 2];
    float4 v1 = src[j * 2 + 1];
    Half8 pack;
    pack.a = __floats2half2_rn(v0.x, v0.y);
    pack.b = __floats2half2_rn(v0.z, v0.w);
    pack.c = __floats2half2_rn(v1.x, v1.y);
    pack.d = __floats2half2_rn(v1.z, v1.w);
    *reinterpret_cast<Half8*>(dst + (size_t)j * 8) = pack;
}

// ------------------------------- launch -------------------------------------

extern "C" void kernel_launch(void* const* d_in, const int* in_sizes, int n_in,
                              void* d_out, int out_size)
{
    const float* X  = (const float*)d_in[0]; // [M, D]
    const float* W1 = (const float*)d_in[1]; // [F, D]
    const float* b1 = (const float*)d_in[2]; // [F]
    const float* W2 = (const float*)d_in[3]; // [D, F]
    const float* b2 = (const float*)d_in[4]; // [D]
    float* out = (float*)d_out;              // [M, D]

    const int F = in_sizes[2];               // 4096
    const int D = in_sizes[4];               // 1024
    const int M = in_sizes[0] / D;           // 8192

    __half *midh, *Xh, *W1h, *W2h;
    cudaGetSymbolAddress((void**)&midh, g_midh);
    cudaGetSymbolAddress((void**)&Xh,   g_Xh);
    cudaGetSymbolAddress((void**)&W1h,  g_W1h);
    cudaGetSymbolAddress((void**)&W2h,  g_W2h);

    cudaFuncSetAttribute(ffn_gemm<true,  true >,
                         cudaFuncAttributeMaxDynamicSharedMemorySize, SMEM_DYN);
    cudaFuncSetAttribute(ffn_gemm<false, false>,
                         cudaFuncAttributeMaxDynamicSharedMemorySize, SMEM_DYN);

    // Convert inputs to fp16 (RN). One launch; index = groups of 8 floats.
    const int n1 = (M * D) / 8, n2 = (F * D) / 8, n3 = (D * F) / 8;
    const int ntot = n1 + n2 + n3;
    to_half_fused<<<(ntot + 255) / 256, 256>>>(
        (const float4*)X,  Xh,  n1,
        (const float4*)W1, W1h, n2,
        (const float4*)W2, W2h, n3);

    // GEMM1: midh = half(swish(X @ W1^T + b1))   [M, F], K = D
    {
        dim3 grid(F / BN, M / BM);
        ffn_gemm<true, true><<<grid, NTHREADS, SMEM_DYN>>>(Xh, W1h, b1, midh, M, F, D);
    }
    // GEMM2: out = midh @ W2^T + b2               [M, D], K = F
    {
        dim3 grid(D / BN, M / BM);
        ffn_gemm<false, false><<<grid, NTHREADS, SMEM_DYN>>>(midh, W2h, b2, out, M, D, F);
    }
}